// round 2
// baseline (speedup 1.0000x reference)
#include <cuda_runtime.h>
#include <cstdint>

#define BATCH 4
#define NHEAD 8
#define S_LEN 2048
#define FDIM  1024
#define DHEAD 128

// ---------------- scratch (no allocations allowed) ----------------
static __device__ float g_sig[4];                 // inv_sigma per weight (q,k,v,o)
static __device__ float g_v1[4][FDIM];            // u @ W^T (unnormalized)
static __device__ float g_s1[4][FDIM];            // v1 @ W
static __device__ float g_q[(size_t)BATCH*NHEAD*S_LEN*DHEAD];   // [B,H,S,D]
static __device__ float g_k[(size_t)BATCH*NHEAD*S_LEN*DHEAD];
static __device__ float g_v[(size_t)BATCH*NHEAD*S_LEN*DHEAD];
static __device__ float g_ctx[(size_t)BATCH*S_LEN*FDIM];        // merged heads

// ---------------- helpers ----------------
__device__ __forceinline__ float warp_sum(float v){
    #pragma unroll
    for (int o=16;o;o>>=1) v += __shfl_xor_sync(0xffffffffu, v, o);
    return v;
}
__device__ __forceinline__ uint32_t f2tf(float x){
    uint32_t r; asm("cvt.rna.tf32.f32 %0, %1;" : "=r"(r) : "f"(x)); return r;
}
__device__ __forceinline__ void mma8(float* c, const uint32_t* a, const uint32_t* b){
    asm volatile(
        "mma.sync.aligned.m16n8k8.row.col.f32.tf32.tf32.f32 "
        "{%0,%1,%2,%3},{%4,%5,%6,%7},{%8,%9},{%0,%1,%2,%3};\n"
        : "+f"(c[0]), "+f"(c[1]), "+f"(c[2]), "+f"(c[3])
        : "r"(a[0]), "r"(a[1]), "r"(a[2]), "r"(a[3]), "r"(b[0]), "r"(b[1]));
}

// ---------------- spectral norm (exact fp32) ----------------
// v1[i] = sum_j u[j] * W[i][j]   (one warp per row)
__global__ void k_sigma_v(const float* w0,const float* w1,const float* w2,const float* w3,
                          const float* u0,const float* u1,const float* u2,const float* u3){
    const float* Wt[4]={w0,w1,w2,w3};
    const float* Ut[4]={u0,u1,u2,u3};
    int wi = blockIdx.y;
    const float* W = Wt[wi];
    const float* U = Ut[wi];
    int lane = threadIdx.x&31, warp = threadIdx.x>>5;
    int row = blockIdx.x*8 + warp;
    const float* r = W + (size_t)row*FDIM;
    float acc = 0.f;
    for (int j=lane;j<FDIM;j+=32) acc += U[j]*r[j];
    acc = warp_sum(acc);
    if (!lane) g_v1[wi][row] = acc;
}
// s[o] = sum_i v1[i] * W[i][o]   (coalesced columns)
__global__ void k_sigma_s(const float* w0,const float* w1,const float* w2,const float* w3){
    const float* Wt[4]={w0,w1,w2,w3};
    int wi = blockIdx.y;
    const float* W = Wt[wi];
    int o = blockIdx.x*256 + threadIdx.x;
    float acc = 0.f;
    for (int i=0;i<FDIM;i++) acc += g_v1[wi][i]*W[(size_t)i*FDIM+o];
    g_s1[wi][o] = acc;
}
// inv_sigma = ||v1|| / ||s||   (sigma = ||normalize(v1) @ W|| = ||s||/||v1||)
__global__ void k_sigma_fin(){
    __shared__ float rv[8], rs[8];
    int wi = blockIdx.x, tid = threadIdx.x;
    float sv=0.f, ss=0.f;
    for (int i=tid;i<FDIM;i+=256){
        float a=g_v1[wi][i]; sv += a*a;
        float b=g_s1[wi][i]; ss += b*b;
    }
    sv = warp_sum(sv); ss = warp_sum(ss);
    if ((tid&31)==0){ rv[tid>>5]=sv; rs[tid>>5]=ss; }
    __syncthreads();
    if (tid==0){
        float a=0.f,b=0.f;
        for (int i=0;i<8;i++){ a+=rv[i]; b+=rs[i]; }
        g_sig[wi] = sqrtf(a/b);
    }
}

// ---------------- tf32(x3) GEMM ----------------
// C(MxN) = A(MxK) * B, CTA tile 128x128, k-tile 32, 8 warps (2x4), warp tile 64x32.
// BLAY==0: B is [K,N] row-major (n contiguous).  BLAY==1: B is [N,K] row-major (k contig, i.e. C=A*B^T).
// X3: tf32x3 Dekker-split (fp32-class precision).
// EPI: 0 = raw logits -> Dst + z*S*S (row-major SxS)
//      1 = proj: v*sig + bias, head-split write to [B,H,S,D]
//      2 = ctx:  write [B,S,F] merged heads (z = b*8+h, N=128)
//      3 = out:  x0 + (v*sig + bias)*gamma, row-major [B*S, F]
template<int EPI, bool X3, int BLAY>
__global__ void __launch_bounds__(256) gemm_k(
    const float* __restrict__ A0, const float* __restrict__ B0,
    float* __restrict__ Dst, int K, int lda, int ldb,
    const float* __restrict__ sig, const float* __restrict__ bias,
    const float* __restrict__ x0, const float* __restrict__ gammap)
{
    constexpr int ASZ = 128*36;                       // [m][k] padded (stride%32==4: conflict-free frags)
    constexpr int BSZ = (BLAY==1) ? 128*36 : 32*136;  // [n][k] or [k][n] (stride%32==8)
    extern __shared__ uint32_t smem_u[];
    uint32_t* Ah = smem_u;
    uint32_t* Al = smem_u + ASZ;
    uint32_t* Bh = smem_u + (X3?2:1)*ASZ;
    uint32_t* Bl = Bh + BSZ;

    const int tid = threadIdx.x;
    const int lane = tid & 31;
    const int warp = tid >> 5;
    const int wm = warp >> 2;   // 0..1 -> 64-row slab
    const int wn = warp & 3;    // 0..3 -> 32-col slab
    const int rl = lane >> 2;   // 0..7
    const int cl = lane & 3;    // 0..3
    const int z = blockIdx.z;
    const int mblk = blockIdx.y * 128;
    const int nblk = blockIdx.x * 128;

    const float* Ag = A0;
    const float* Bg = B0;
    if (EPI==0){ Ag += (size_t)z*S_LEN*DHEAD; Bg += (size_t)z*S_LEN*DHEAD; }
    if (EPI==2){ Ag += (size_t)z*S_LEN*S_LEN; Bg += (size_t)z*S_LEN*DHEAD; }
    Ag += (size_t)mblk * lda;
    Bg += (BLAY==1) ? (size_t)nblk*ldb : (size_t)nblk;

    float acc[4][4][4];
    #pragma unroll
    for (int i=0;i<4;i++)
        #pragma unroll
        for (int j=0;j<4;j++)
            #pragma unroll
            for (int r=0;r<4;r++) acc[i][j][r]=0.f;

    const int nkt = K >> 5;
    float4 ra[4], rb[4];
    // prefetch tile 0
    #pragma unroll
    for (int i=0;i<4;i++){
        int idx = tid + i*256;
        ra[i] = *reinterpret_cast<const float4*>(Ag + (size_t)(idx>>3)*lda + ((idx&7)<<2));
        if (BLAY==1)
            rb[i] = *reinterpret_cast<const float4*>(Bg + (size_t)(idx>>3)*ldb + ((idx&7)<<2));
        else
            rb[i] = *reinterpret_cast<const float4*>(Bg + (size_t)(idx>>5)*ldb + ((idx&31)<<2));
    }

    for (int kt=0; kt<nkt; kt++){
        __syncthreads();
        // store tile to smem with tf32 hi/lo split
        #pragma unroll
        for (int i=0;i<4;i++){
            int idx = tid + i*256;
            {
                int base = (idx>>3)*36 + ((idx&7)<<2);
                float4 v = ra[i];
                uint32_t h0=f2tf(v.x),h1=f2tf(v.y),h2=f2tf(v.z),h3=f2tf(v.w);
                *reinterpret_cast<uint4*>(&Ah[base]) = make_uint4(h0,h1,h2,h3);
                if (X3){
                    uint32_t l0=f2tf(v.x-__uint_as_float(h0));
                    uint32_t l1=f2tf(v.y-__uint_as_float(h1));
                    uint32_t l2=f2tf(v.z-__uint_as_float(h2));
                    uint32_t l3=f2tf(v.w-__uint_as_float(h3));
                    *reinterpret_cast<uint4*>(&Al[base]) = make_uint4(l0,l1,l2,l3);
                }
            }
            {
                int base = (BLAY==1) ? ((idx>>3)*36 + ((idx&7)<<2))
                                     : ((idx>>5)*136 + ((idx&31)<<2));
                float4 v = rb[i];
                uint32_t h0=f2tf(v.x),h1=f2tf(v.y),h2=f2tf(v.z),h3=f2tf(v.w);
                *reinterpret_cast<uint4*>(&Bh[base]) = make_uint4(h0,h1,h2,h3);
                if (X3){
                    uint32_t l0=f2tf(v.x-__uint_as_float(h0));
                    uint32_t l1=f2tf(v.y-__uint_as_float(h1));
                    uint32_t l2=f2tf(v.z-__uint_as_float(h2));
                    uint32_t l3=f2tf(v.w-__uint_as_float(h3));
                    *reinterpret_cast<uint4*>(&Bl[base]) = make_uint4(l0,l1,l2,l3);
                }
            }
        }
        __syncthreads();
        // advance, prefetch next tile (latency hidden behind MMA)
        Ag += 32;
        Bg += (BLAY==1) ? 32 : (size_t)32*ldb;
        if (kt+1 < nkt){
            #pragma unroll
            for (int i=0;i<4;i++){
                int idx = tid + i*256;
                ra[i] = *reinterpret_cast<const float4*>(Ag + (size_t)(idx>>3)*lda + ((idx&7)<<2));
                if (BLAY==1)
                    rb[i] = *reinterpret_cast<const float4*>(Bg + (size_t)(idx>>3)*ldb + ((idx&7)<<2));
                else
                    rb[i] = *reinterpret_cast<const float4*>(Bg + (size_t)(idx>>5)*ldb + ((idx&31)<<2));
            }
        }
        // compute 4 k-steps of 8
        #pragma unroll
        for (int ks=0; ks<4; ks++){
            const int kb = ks*8;
            uint32_t ah[4][4], al[4][4], bhf[4][2], blf[4][2];
            #pragma unroll
            for (int mt=0; mt<4; mt++){
                int base = (wm*64 + mt*16 + rl)*36 + kb + cl;
                ah[mt][0]=Ah[base];        ah[mt][1]=Ah[base+8*36];
                ah[mt][2]=Ah[base+4];      ah[mt][3]=Ah[base+8*36+4];
                if (X3){
                    al[mt][0]=Al[base];    al[mt][1]=Al[base+8*36];
                    al[mt][2]=Al[base+4];  al[mt][3]=Al[base+8*36+4];
                }
            }
            #pragma unroll
            for (int nt=0; nt<4; nt++){
                if (BLAY==1){
                    int base = (wn*32 + nt*8 + rl)*36 + kb + cl;
                    bhf[nt][0]=Bh[base]; bhf[nt][1]=Bh[base+4];
                    if (X3){ blf[nt][0]=Bl[base]; blf[nt][1]=Bl[base+4]; }
                } else {
                    int base = (kb + cl)*136 + wn*32 + nt*8 + rl;
                    bhf[nt][0]=Bh[base]; bhf[nt][1]=Bh[base+4*136];
                    if (X3){ blf[nt][0]=Bl[base]; blf[nt][1]=Bl[base+4*136]; }
                }
            }
            #pragma unroll
            for (int mt=0; mt<4; mt++)
                #pragma unroll
                for (int nt=0; nt<4; nt++){
                    mma8(acc[mt][nt], ah[mt], bhf[nt]);
                    if (X3){
                        mma8(acc[mt][nt], ah[mt], blf[nt]);
                        mma8(acc[mt][nt], al[mt], bhf[nt]);
                    }
                }
        }
    }

    // epilogue
    float sg = 1.f, gm = 1.f;
    if (EPI==1 || EPI==3) sg = *sig;
    if (EPI==3) gm = *gammap;
    #pragma unroll
    for (int mt=0; mt<4; mt++){
        #pragma unroll
        for (int nt=0; nt<4; nt++){
            int row0 = mblk + wm*64 + mt*16 + rl;
            int col  = nblk + wn*32 + nt*8 + 2*cl;
            #pragma unroll
            for (int h2=0; h2<2; h2++){
                int row = row0 + h2*8;
                float v0 = acc[mt][nt][h2*2+0];
                float v1 = acc[mt][nt][h2*2+1];
                if (EPI==0){
                    *reinterpret_cast<float2*>(Dst + (size_t)z*S_LEN*S_LEN + (size_t)row*S_LEN + col)
                        = make_float2(v0, v1);
                } else if (EPI==1){
                    float o0 = v0*sg + bias[col];
                    float o1 = v1*sg + bias[col+1];
                    int b = row >> 11, s = row & (S_LEN-1);
                    int h = col >> 7, d = col & (DHEAD-1);
                    *reinterpret_cast<float2*>(Dst + (((size_t)(b*NHEAD+h)*S_LEN + s)*DHEAD + d))
                        = make_float2(o0, o1);
                } else if (EPI==2){
                    int b = z >> 3, h = z & 7;
                    *reinterpret_cast<float2*>(Dst + ((size_t)b*S_LEN + row)*FDIM + h*DHEAD + col)
                        = make_float2(v0, v1);
                } else {
                    size_t idx = (size_t)row*FDIM + col;
                    float o0 = x0[idx]   + (v0*sg + bias[col])*gm;
                    float o1 = x0[idx+1] + (v1*sg + bias[col+1])*gm;
                    *reinterpret_cast<float2*>(Dst + idx) = make_float2(o0, o1);
                }
            }
        }
    }
}

// ---------------- softmax (in-place, one block per row of 2048) ----------------
__global__ void __launch_bounds__(256) k_softmax(float* __restrict__ attn){
    __shared__ float red[8];
    __shared__ float bval;
    float* p = attn + (size_t)blockIdx.x * S_LEN;
    int tid = threadIdx.x, lane = tid&31, warp = tid>>5;
    float4 a = *reinterpret_cast<float4*>(p + tid*8);
    float4 b = *reinterpret_cast<float4*>(p + tid*8 + 4);
    float m = fmaxf(fmaxf(fmaxf(a.x,a.y),fmaxf(a.z,a.w)),
                    fmaxf(fmaxf(b.x,b.y),fmaxf(b.z,b.w)));
    #pragma unroll
    for (int o=16;o;o>>=1) m = fmaxf(m, __shfl_xor_sync(0xffffffffu,m,o));
    if (!lane) red[warp]=m;
    __syncthreads();
    if (tid==0){ float t=red[0]; for(int i=1;i<8;i++) t=fmaxf(t,red[i]); bval=t; }
    __syncthreads();
    m = bval;
    a.x=expf(a.x-m); a.y=expf(a.y-m); a.z=expf(a.z-m); a.w=expf(a.w-m);
    b.x=expf(b.x-m); b.y=expf(b.y-m); b.z=expf(b.z-m); b.w=expf(b.w-m);
    float s = ((a.x+a.y)+(a.z+a.w)) + ((b.x+b.y)+(b.z+b.w));
    s = warp_sum(s);
    __syncthreads();
    if (!lane) red[warp]=s;
    __syncthreads();
    if (tid==0){ float t=0.f; for(int i=0;i<8;i++) t+=red[i]; bval=t; }
    __syncthreads();
    float inv = 1.f/bval;
    a.x*=inv; a.y*=inv; a.z*=inv; a.w*=inv;
    b.x*=inv; b.y*=inv; b.z*=inv; b.w*=inv;
    *reinterpret_cast<float4*>(p + tid*8)     = a;
    *reinterpret_cast<float4*>(p + tid*8 + 4) = b;
}

// ---------------- launch ----------------
extern "C" void kernel_launch(void* const* d_in, const int* in_sizes, int n_in,
                              void* d_out, int out_size)
{
    (void)in_sizes; (void)n_in; (void)out_size;
    const float* x  = (const float*)d_in[0];
    const float* wq = (const float*)d_in[1];
    const float* bq = (const float*)d_in[2];
    const float* uq = (const float*)d_in[3];
    const float* wk = (const float*)d_in[4];
    const float* bk = (const float*)d_in[5];
    const float* uk = (const float*)d_in[6];
    const float* wv = (const float*)d_in[7];
    const float* bv = (const float*)d_in[8];
    const float* uv = (const float*)d_in[9];
    const float* wo = (const float*)d_in[10];
    const float* bo = (const float*)d_in[11];
    const float* uo = (const float*)d_in[12];
    const float* gm = (const float*)d_in[13];

    float* out  = (float*)d_out;
    float* attn = out + (size_t)BATCH*S_LEN*FDIM;

    float *pq,*pk,*pv,*pctx,*psig;
    cudaGetSymbolAddress((void**)&pq,   g_q);
    cudaGetSymbolAddress((void**)&pk,   g_k);
    cudaGetSymbolAddress((void**)&pv,   g_v);
    cudaGetSymbolAddress((void**)&pctx, g_ctx);
    cudaGetSymbolAddress((void**)&psig, g_sig);

    cudaFuncSetAttribute(gemm_k<1,true,0>,  cudaFuncAttributeMaxDynamicSharedMemorySize, 71680);
    cudaFuncSetAttribute(gemm_k<3,true,0>,  cudaFuncAttributeMaxDynamicSharedMemorySize, 71680);
    cudaFuncSetAttribute(gemm_k<0,true,1>,  cudaFuncAttributeMaxDynamicSharedMemorySize, 73728);

    // spectral norms (exact fp32)
    k_sigma_v<<<dim3(128,4),256>>>(wq,wk,wv,wo, uq,uk,uv,uo);
    k_sigma_s<<<dim3(4,4),256>>>(wq,wk,wv,wo);
    k_sigma_fin<<<4,256>>>();

    // projections (tf32x3, head-split epilogue)
    gemm_k<1,true,0><<<dim3(8,64,1),256,71680>>>(x, wq, pq, FDIM, FDIM, FDIM, psig+0, bq, nullptr, nullptr);
    gemm_k<1,true,0><<<dim3(8,64,1),256,71680>>>(x, wk, pk, FDIM, FDIM, FDIM, psig+1, bk, nullptr, nullptr);
    gemm_k<1,true,0><<<dim3(8,64,1),256,71680>>>(x, wv, pv, FDIM, FDIM, FDIM, psig+2, bv, nullptr, nullptr);

    // logits = q k^T (tf32x3), written raw into the attn output region
    gemm_k<0,true,1><<<dim3(16,16,32),256,73728>>>(pq, pk, attn, DHEAD, DHEAD, DHEAD,
                                                   nullptr,nullptr,nullptr,nullptr);
    // softmax in place
    k_softmax<<<BATCH*NHEAD*S_LEN,256>>>(attn);

    // ctx = attn @ v (tf32 x1 is safe here), merged-head layout
    gemm_k<2,false,0><<<dim3(1,16,32),256,35840>>>(attn, pv, pctx, S_LEN, S_LEN, DHEAD,
                                                   nullptr,nullptr,nullptr,nullptr);
    // out = x + (ctx @ wo_n + bo) * gamma (tf32x3)
    gemm_k<3,true,0><<<dim3(8,64,1),256,71680>>>(pctx, wo, out, FDIM, FDIM, FDIM, psig+3, bo, x, gm);
}